// round 1
// baseline (speedup 1.0000x reference)
#include <cuda_runtime.h>

// FourierConv2D via DFT-as-GEMM (fp32).
//   F[b,c]   = A @ X[b,c] @ A^T          A: 511x256 complex DFT slab (input zero-padded)
//   G[b,o]   = sum_c F[b,c] * W[o,c]     pointwise complex, W given in freq domain
//   out[b,o] = Re( E @ G[b,o] @ E^T )+bias   E: 256x511 inverse slab restricted to crop
//                                            rows (y+127), 1/511 folded into each E.

namespace {
constexpr int N5   = 511;
constexpr int HH   = 256;
constexpr int NB   = 4;
constexpr int NCIN = 4;
constexpr int NCOUT= 8;
constexpr int PLANE= N5 * N5;       // 261121
constexpr int BC   = NB * NCIN;     // 16
constexpr int BO   = NB * NCOUT;    // 32
}

// ---- scratch (device globals; no allocation allowed) ----
__device__ float g_Ar[N5*HH],  g_Ai[N5*HH];    // A[k][n] = exp(-2pi i k n/511)
__device__ float g_Er[HH*N5],  g_Ei[HH*N5];    // E[x][k] = exp(+2pi i k (x+127)/511)/511
__device__ float g_T1r[BC*N5*HH], g_T1i[BC*N5*HH];
__device__ float g_Fr[BC*PLANE],  g_Fi[BC*PLANE];
__device__ float g_Gr[BO*PLANE],  g_Gi[BO*PLANE];
__device__ float g_T2r[BO*N5*HH], g_T2i[BO*N5*HH];

// ---- twiddle init (recomputed every launch; cheap) ----
__global__ void k_twiddle() {
    int idx = blockIdx.x * blockDim.x + threadIdx.x;
    if (idx >= N5 * HH) return;                 // both tables have 130816 entries
    {
        int k = idx / HH, n = idx - k * HH;
        int m = (k * n) % N5;                   // exact int reduction
        float ang = 6.283185307179586f * (float)m / (float)N5;
        float s, c; sincosf(ang, &s, &c);
        g_Ar[idx] = c;  g_Ai[idx] = -s;
    }
    {
        int x = idx / N5, k = idx - x * N5;
        int m = (k * (x + 127)) % N5;
        float ang = 6.283185307179586f * (float)m / (float)N5;
        float s, c; sincosf(ang, &s, &c);
        const float inv = 1.0f / (float)N5;
        g_Er[idx] = c * inv;  g_Ei[idx] = s * inv;
    }
}

// ---- stage 1: T1[z] (511x256 cplx) = A (511x256 cplx) @ X[z] (256x256 real) ----
__global__ void k_stage1(const float* __restrict__ im) {
    const int z = blockIdx.z;                   // b*CIN + c
    const float* __restrict__ X = im + (size_t)z * HH * HH;
    float* __restrict__ Cr = g_T1r + (size_t)z * N5 * HH;
    float* __restrict__ Ci = g_T1i + (size_t)z * N5 * HH;

    __shared__ float Asr[16][68], Asi[16][68], Bs[16][68];
    const int tx = threadIdx.x, ty = threadIdx.y;
    const int tid = ty * 16 + tx;
    const int m0 = blockIdx.y * 64, n0 = blockIdx.x * 64;
    const int ra = tid >> 2, ka = (tid & 3) * 4;       // A-tile: row, k-chunk
    const int kb = tid >> 4, nb = (tid & 15) * 4;      // B-tile: k-row, n-chunk

    float cr[4][4] = {}, ci[4][4] = {};

    for (int k0 = 0; k0 < HH; k0 += 16) {
        const int gm = m0 + ra;
        #pragma unroll
        for (int j = 0; j < 4; j++) {
            const int gk = k0 + ka + j;
            float vr = 0.f, vi = 0.f;
            if (gm < N5) { vr = g_Ar[gm*HH + gk]; vi = g_Ai[gm*HH + gk]; }
            Asr[ka + j][ra] = vr;
            Asi[ka + j][ra] = vi;
        }
        #pragma unroll
        for (int j = 0; j < 4; j++)
            Bs[kb][nb + j] = X[(k0 + kb)*HH + n0 + nb + j];
        __syncthreads();

        #pragma unroll
        for (int k = 0; k < 16; k++) {
            float4 arv = *reinterpret_cast<const float4*>(&Asr[k][ty*4]);
            float4 aiv = *reinterpret_cast<const float4*>(&Asi[k][ty*4]);
            float4 bv  = *reinterpret_cast<const float4*>(&Bs[k][tx*4]);
            const float ar[4] = {arv.x, arv.y, arv.z, arv.w};
            const float ai[4] = {aiv.x, aiv.y, aiv.z, aiv.w};
            const float b [4] = {bv.x,  bv.y,  bv.z,  bv.w};
            #pragma unroll
            for (int i = 0; i < 4; i++)
                #pragma unroll
                for (int j = 0; j < 4; j++) {
                    cr[i][j] += ar[i] * b[j];
                    ci[i][j] += ai[i] * b[j];
                }
        }
        __syncthreads();
    }
    #pragma unroll
    for (int i = 0; i < 4; i++) {
        const int gm = m0 + ty*4 + i;
        if (gm >= N5) continue;
        #pragma unroll
        for (int j = 0; j < 4; j++) {
            const int gn = n0 + tx*4 + j;
            Cr[gm*HH + gn] = cr[i][j];
            Ci[gm*HH + gn] = ci[i][j];
        }
    }
}

// ---- complex GEMM, B accessed transposed:  C(MxN) = A(MxK) @ B(NxK)^T ----
template<int M, int N, int K>
__device__ __forceinline__ void gemm_ccbt_body(
    const float* __restrict__ Ar, const float* __restrict__ Ai,
    const float* __restrict__ Br, const float* __restrict__ Bi,
    float* __restrict__ Cr, float* __restrict__ Ci)
{
    __shared__ float Asr[16][68], Asi[16][68], Bsr[16][68], Bsi[16][68];
    const int tx = threadIdx.x, ty = threadIdx.y;
    const int tid = ty * 16 + tx;
    const int m0 = blockIdx.y * 64, n0 = blockIdx.x * 64;
    const int ra = tid >> 2, ka = (tid & 3) * 4;

    float cr[4][4] = {}, ci[4][4] = {};

    for (int k0 = 0; k0 < K; k0 += 16) {
        {   const int gm = m0 + ra;
            #pragma unroll
            for (int j = 0; j < 4; j++) {
                const int gk = k0 + ka + j;
                float vr = 0.f, vi = 0.f;
                if (gm < M && gk < K) { vr = Ar[gm*K + gk]; vi = Ai[gm*K + gk]; }
                Asr[ka + j][ra] = vr;
                Asi[ka + j][ra] = vi;
            }
        }
        {   const int gn = n0 + ra;
            #pragma unroll
            for (int j = 0; j < 4; j++) {
                const int gk = k0 + ka + j;
                float vr = 0.f, vi = 0.f;
                if (gn < N && gk < K) { vr = Br[gn*K + gk]; vi = Bi[gn*K + gk]; }
                Bsr[ka + j][ra] = vr;
                Bsi[ka + j][ra] = vi;
            }
        }
        __syncthreads();
        #pragma unroll
        for (int k = 0; k < 16; k++) {
            float4 arv = *reinterpret_cast<const float4*>(&Asr[k][ty*4]);
            float4 aiv = *reinterpret_cast<const float4*>(&Asi[k][ty*4]);
            float4 brv = *reinterpret_cast<const float4*>(&Bsr[k][tx*4]);
            float4 biv = *reinterpret_cast<const float4*>(&Bsi[k][tx*4]);
            const float ar[4] = {arv.x, arv.y, arv.z, arv.w};
            const float ai[4] = {aiv.x, aiv.y, aiv.z, aiv.w};
            const float br[4] = {brv.x, brv.y, brv.z, brv.w};
            const float bi[4] = {biv.x, biv.y, biv.z, biv.w};
            #pragma unroll
            for (int i = 0; i < 4; i++)
                #pragma unroll
                for (int j = 0; j < 4; j++) {
                    cr[i][j] += ar[i] * br[j] - ai[i] * bi[j];
                    ci[i][j] += ar[i] * bi[j] + ai[i] * br[j];
                }
        }
        __syncthreads();
    }
    #pragma unroll
    for (int i = 0; i < 4; i++) {
        const int gm = m0 + ty*4 + i;
        if (gm >= M) continue;
        #pragma unroll
        for (int j = 0; j < 4; j++) {
            const int gn = n0 + tx*4 + j;
            if (gn >= N) continue;
            Cr[gm*N + gn] = cr[i][j];
            Ci[gm*N + gn] = ci[i][j];
        }
    }
}

// stage 2: F[z] (511x511) = T1[z] (511x256) @ A(511x256)^T
__global__ void k_stage2() {
    const int z = blockIdx.z;
    const size_t sa = (size_t)N5 * HH, sc = (size_t)PLANE;
    gemm_ccbt_body<N5, N5, HH>(g_T1r + z*sa, g_T1i + z*sa,
                               g_Ar, g_Ai,
                               g_Fr + z*sc, g_Fi + z*sc);
}

// stage 4: T2[z] (511x256) = G[z] (511x511) @ E(256x511)^T
__global__ void k_stage4() {
    const int z = blockIdx.z;
    const size_t sa = (size_t)PLANE, sc = (size_t)N5 * HH;
    gemm_ccbt_body<N5, HH, N5>(g_Gr + z*sa, g_Gi + z*sa,
                               g_Er, g_Ei,
                               g_T2r + z*sc, g_T2i + z*sc);
}

// ---- stage 3: pointwise freq-domain multiply + cin reduction ----
__global__ void k_pointwise(const float* __restrict__ w) {
    const int p = blockIdx.x * blockDim.x + threadIdx.x;
    if (p >= PLANE) return;
    const int o = blockIdx.y, b = blockIdx.z;
    float gr = 0.f, gi = 0.f;
    #pragma unroll
    for (int c = 0; c < NCIN; c++) {
        const float fr = g_Fr[(size_t)(b*NCIN + c)*PLANE + p];
        const float fi = g_Fi[(size_t)(b*NCIN + c)*PLANE + p];
        const float2 wv = *reinterpret_cast<const float2*>(
            w + ((size_t)(o*NCIN + c)*PLANE + p) * 2);
        gr += fr * wv.x - fi * wv.y;
        gi += fr * wv.y + fi * wv.x;
    }
    g_Gr[(size_t)(b*NCOUT + o)*PLANE + p] = gr;
    g_Gi[(size_t)(b*NCOUT + o)*PLANE + p] = gi;
}

// ---- stage 5: out[z] (256x256 real) = Re( E(256x511) @ T2[z](511x256) ) + bias ----
__global__ void k_stage5(const float* __restrict__ bias, float* __restrict__ out) {
    const int z = blockIdx.z;                   // b*NCOUT + o
    const float* __restrict__ Br = g_T2r + (size_t)z * N5 * HH;
    const float* __restrict__ Bi = g_T2i + (size_t)z * N5 * HH;
    float* __restrict__ O = out + (size_t)z * HH * HH;

    __shared__ float Aer[16][68], Aei[16][68], Bsr[16][68], Bsi[16][68];
    const int tx = threadIdx.x, ty = threadIdx.y;
    const int tid = ty * 16 + tx;
    const int m0 = blockIdx.y * 64, n0 = blockIdx.x * 64;
    const int ra = tid >> 2, ka = (tid & 3) * 4;
    const int kb = tid >> 4, nb = (tid & 15) * 4;

    float acc[4][4] = {};

    for (int k0 = 0; k0 < N5; k0 += 16) {
        {   const int gm = m0 + ra;
            #pragma unroll
            for (int j = 0; j < 4; j++) {
                const int gk = k0 + ka + j;
                float vr = 0.f, vi = 0.f;
                if (gk < N5) { vr = g_Er[gm*N5 + gk]; vi = g_Ei[gm*N5 + gk]; }
                Aer[ka + j][ra] = vr;
                Aei[ka + j][ra] = vi;
            }
        }
        {   const int gk = k0 + kb;
            #pragma unroll
            for (int j = 0; j < 4; j++) {
                float vr = 0.f, vi = 0.f;
                if (gk < N5) {
                    vr = Br[gk*HH + n0 + nb + j];
                    vi = Bi[gk*HH + n0 + nb + j];
                }
                Bsr[kb][nb + j] = vr;
                Bsi[kb][nb + j] = vi;
            }
        }
        __syncthreads();
        #pragma unroll
        for (int k = 0; k < 16; k++) {
            float4 erv = *reinterpret_cast<const float4*>(&Aer[k][ty*4]);
            float4 eiv = *reinterpret_cast<const float4*>(&Aei[k][ty*4]);
            float4 brv = *reinterpret_cast<const float4*>(&Bsr[k][tx*4]);
            float4 biv = *reinterpret_cast<const float4*>(&Bsi[k][tx*4]);
            const float er[4] = {erv.x, erv.y, erv.z, erv.w};
            const float ei[4] = {eiv.x, eiv.y, eiv.z, eiv.w};
            const float br[4] = {brv.x, brv.y, brv.z, brv.w};
            const float bi[4] = {biv.x, biv.y, biv.z, biv.w};
            #pragma unroll
            for (int i = 0; i < 4; i++)
                #pragma unroll
                for (int j = 0; j < 4; j++)
                    acc[i][j] += er[i] * br[j] - ei[i] * bi[j];
        }
        __syncthreads();
    }
    const float bv = bias[z & 7];               // z % NCOUT
    #pragma unroll
    for (int i = 0; i < 4; i++) {
        const int gm = m0 + ty*4 + i;
        #pragma unroll
        for (int j = 0; j < 4; j++) {
            const int gn = n0 + tx*4 + j;
            O[gm*HH + gn] = acc[i][j] + bv;
        }
    }
}

extern "C" void kernel_launch(void* const* d_in, const int* in_sizes, int n_in,
                              void* d_out, int out_size) {
    (void)in_sizes; (void)n_in; (void)out_size;
    const float* im   = (const float*)d_in[0];  // [4,4,256,256]
    const float* w    = (const float*)d_in[1];  // [8,4,511,511,2]
    const float* bias = (const float*)d_in[2];  // [8,1,1]
    float* out = (float*)d_out;                 // [4,8,256,256]

    const dim3 blk(16, 16);
    k_twiddle<<<(N5*HH + 255) / 256, 256>>>();
    k_stage1 <<<dim3(4, 8, BC), blk>>>(im);                       // N=256/64, M=511/64
    k_stage2 <<<dim3(8, 8, BC), blk>>>();                         // N=511/64, M=511/64
    k_pointwise<<<dim3((PLANE + 255) / 256, NCOUT, NB), 256>>>(w);
    k_stage4 <<<dim3(4, 8, BO), blk>>>();                         // N=256/64, M=511/64
    k_stage5 <<<dim3(4, 4, BO), blk>>>(bias, out);                // N=256/64, M=256/64
}

// round 3
// speedup vs baseline: 1.8101x; 1.8101x over previous
#include <cuda_runtime.h>

// FourierConv2D via DFT-as-GEMM (fp32) + Hermitian half-plane symmetry.
//   Real input  => F[-k] = conj(F[k])  => only ky=0..255 of the 511-row plane needed.
//   Re(ifft(F*W)) = ifft(F*W_h), W_h = Hermitian part of W  => G stays Hermitian.
//   Final row-inverse folds ky and (511-ky) into one real GEMM with 2x weights.

namespace {
constexpr int N5    = 511;
constexpr int HH    = 256;
constexpr int NB    = 4;
constexpr int NCIN  = 4;
constexpr int NCOUT = 8;
constexpr int PLANE = N5 * N5;       // full-plane elements (W layout)
constexpr int HALF  = HH * N5;       // half-plane elements (ky=0..255)
constexpr int BC    = NB * NCIN;     // 16
constexpr int BO    = NB * NCOUT;    // 32
}

// ---- scratch (device globals; no allocation allowed) ----
__device__ float g_Ar[N5*HH],  g_Ai[N5*HH];    // A[k][n]  = exp(-2pi i k n/511)
__device__ float g_Er[HH*N5],  g_Ei[HH*N5];    // Ec[x][k] = exp(+2pi i k (x+127)/511)/511
__device__ float g_E5r[HH*HH], g_E5i[HH*HH];   // E5[y][ky]= w(ky) * exp(+2pi i ky (y+127)/511), w=1/511 (ky=0) else 2/511
__device__ float g_T1r[BC*HH*HH], g_T1i[BC*HH*HH];
__device__ float g_Fr[BC*HALF],   g_Fi[BC*HALF];
__device__ float g_Gr[BO*HALF],   g_Gi[BO*HALF];
__device__ float g_T2r[BO*HH*HH], g_T2i[BO*HH*HH];

// ---- twiddle init (recomputed every launch; cheap) ----
__global__ void k_twiddle() {
    const int idx = blockIdx.x * blockDim.x + threadIdx.x;
    const float TWO_PI = 6.283185307179586f;
    if (idx < N5 * HH) {
        {   int k = idx / HH, n = idx - k * HH;
            int m = (k * n) % N5;                         // exact int reduction
            float s, c; sincosf(TWO_PI * (float)m / (float)N5, &s, &c);
            g_Ar[idx] = c;  g_Ai[idx] = -s;
        }
        {   int x = idx / N5, k = idx - x * N5;
            int m = (k * (x + 127)) % N5;
            float s, c; sincosf(TWO_PI * (float)m / (float)N5, &s, &c);
            const float inv = 1.0f / (float)N5;
            g_Er[idx] = c * inv;  g_Ei[idx] = s * inv;
        }
    }
    if (idx < HH * HH) {
        int y = idx / HH, ky = idx - y * HH;
        int m = (ky * (y + 127)) % N5;
        float s, c; sincosf(TWO_PI * (float)m / (float)N5, &s, &c);
        const float w = (ky == 0) ? (1.0f / (float)N5) : (2.0f / (float)N5);
        g_E5r[idx] = c * w;  g_E5i[idx] = s * w;
    }
}

// ---- stage 1: T1[z] (256x256 cplx) = A[0:256] (cplx) @ X[z] (256x256 real) ----
__global__ void k_stage1(const float* __restrict__ im) {
    const int z = blockIdx.z;                   // b*CIN + c
    const float* __restrict__ X = im + (size_t)z * HH * HH;
    float* __restrict__ Cr = g_T1r + (size_t)z * HH * HH;
    float* __restrict__ Ci = g_T1i + (size_t)z * HH * HH;

    __shared__ float Asr[16][68], Asi[16][68], Bs[16][68];
    const int tx = threadIdx.x, ty = threadIdx.y;
    const int tid = ty * 16 + tx;
    const int m0 = blockIdx.y * 64, n0 = blockIdx.x * 64;
    const int ra = tid >> 2, ka = (tid & 3) * 4;
    const int kb = tid >> 4, nb = (tid & 15) * 4;

    float cr[4][4] = {}, ci[4][4] = {};

    for (int k0 = 0; k0 < HH; k0 += 16) {
        const int gm = m0 + ra;                 // 0..255, A rows 0..255 of g_Ar
        #pragma unroll
        for (int j = 0; j < 4; j++) {
            const int gk = k0 + ka + j;
            Asr[ka + j][ra] = g_Ar[gm*HH + gk];
            Asi[ka + j][ra] = g_Ai[gm*HH + gk];
        }
        #pragma unroll
        for (int j = 0; j < 4; j++)
            Bs[kb][nb + j] = X[(k0 + kb)*HH + n0 + nb + j];
        __syncthreads();

        #pragma unroll
        for (int k = 0; k < 16; k++) {
            float4 arv = *reinterpret_cast<const float4*>(&Asr[k][ty*4]);
            float4 aiv = *reinterpret_cast<const float4*>(&Asi[k][ty*4]);
            float4 bv  = *reinterpret_cast<const float4*>(&Bs[k][tx*4]);
            const float ar[4] = {arv.x, arv.y, arv.z, arv.w};
            const float ai[4] = {aiv.x, aiv.y, aiv.z, aiv.w};
            const float b [4] = {bv.x,  bv.y,  bv.z,  bv.w};
            #pragma unroll
            for (int i = 0; i < 4; i++)
                #pragma unroll
                for (int j = 0; j < 4; j++) {
                    cr[i][j] += ar[i] * b[j];
                    ci[i][j] += ai[i] * b[j];
                }
        }
        __syncthreads();
    }
    #pragma unroll
    for (int i = 0; i < 4; i++) {
        const int gm = m0 + ty*4 + i;
        #pragma unroll
        for (int j = 0; j < 4; j++) {
            const int gn = n0 + tx*4 + j;
            Cr[gm*HH + gn] = cr[i][j];
            Ci[gm*HH + gn] = ci[i][j];
        }
    }
}

// ---- complex GEMM, B accessed transposed:  C(MxN) = A(MxK) @ B(NxK)^T ----
// CHK_N / CHK_K enable bounds predicates only where a dim is not tile-divisible.
template<int M, int N, int K, bool CHK_N, bool CHK_K>
__device__ __forceinline__ void gemm_ccbt_body(
    const float* __restrict__ Ar, const float* __restrict__ Ai,
    const float* __restrict__ Br, const float* __restrict__ Bi,
    float* __restrict__ Cr, float* __restrict__ Ci)
{
    __shared__ float Asr[16][68], Asi[16][68], Bsr[16][68], Bsi[16][68];
    const int tx = threadIdx.x, ty = threadIdx.y;
    const int tid = ty * 16 + tx;
    const int m0 = blockIdx.y * 64, n0 = blockIdx.x * 64;
    const int ra = tid >> 2, ka = (tid & 3) * 4;

    float cr[4][4] = {}, ci[4][4] = {};

    for (int k0 = 0; k0 < K; k0 += 16) {
        {   const int gm = m0 + ra;
            #pragma unroll
            for (int j = 0; j < 4; j++) {
                const int gk = k0 + ka + j;
                float vr = 0.f, vi = 0.f;
                if (!CHK_K || gk < K) { vr = Ar[(size_t)gm*K + gk]; vi = Ai[(size_t)gm*K + gk]; }
                Asr[ka + j][ra] = vr;
                Asi[ka + j][ra] = vi;
            }
        }
        {   const int gn = n0 + ra;
            #pragma unroll
            for (int j = 0; j < 4; j++) {
                const int gk = k0 + ka + j;
                float vr = 0.f, vi = 0.f;
                if ((!CHK_N || gn < N) && (!CHK_K || gk < K)) {
                    vr = Br[(size_t)gn*K + gk]; vi = Bi[(size_t)gn*K + gk];
                }
                Bsr[ka + j][ra] = vr;
                Bsi[ka + j][ra] = vi;
            }
        }
        __syncthreads();
        #pragma unroll
        for (int k = 0; k < 16; k++) {
            float4 arv = *reinterpret_cast<const float4*>(&Asr[k][ty*4]);
            float4 aiv = *reinterpret_cast<const float4*>(&Asi[k][ty*4]);
            float4 brv = *reinterpret_cast<const float4*>(&Bsr[k][tx*4]);
            float4 biv = *reinterpret_cast<const float4*>(&Bsi[k][tx*4]);
            const float ar[4] = {arv.x, arv.y, arv.z, arv.w};
            const float ai[4] = {aiv.x, aiv.y, aiv.z, aiv.w};
            const float br[4] = {brv.x, brv.y, brv.z, brv.w};
            const float bi[4] = {biv.x, biv.y, biv.z, biv.w};
            #pragma unroll
            for (int i = 0; i < 4; i++)
                #pragma unroll
                for (int j = 0; j < 4; j++) {
                    cr[i][j] += ar[i] * br[j] - ai[i] * bi[j];
                    ci[i][j] += ar[i] * bi[j] + ai[i] * br[j];
                }
        }
        __syncthreads();
    }
    #pragma unroll
    for (int i = 0; i < 4; i++) {
        const int gm = m0 + ty*4 + i;
        #pragma unroll
        for (int j = 0; j < 4; j++) {
            const int gn = n0 + tx*4 + j;
            if (!CHK_N || gn < N) {
                Cr[(size_t)gm*N + gn] = cr[i][j];
                Ci[(size_t)gm*N + gn] = ci[i][j];
            }
        }
    }
}

// stage 2: F[z] (256x511) = T1[z] (256x256) @ A(511x256)^T
__global__ void k_stage2() {
    const int z = blockIdx.z;
    const size_t sa = (size_t)HH * HH, sc = (size_t)HALF;
    gemm_ccbt_body<HH, N5, HH, true, false>(g_T1r + z*sa, g_T1i + z*sa,
                                            g_Ar, g_Ai,
                                            g_Fr + z*sc, g_Fi + z*sc);
}

// stage 4: T2[z] (256x256) = G[z] (256x511) @ Ec(256x511)^T
__global__ void k_stage4() {
    const int z = blockIdx.z;
    const size_t sa = (size_t)HALF, sc = (size_t)HH * HH;
    gemm_ccbt_body<HH, HH, N5, false, true>(g_Gr + z*sa, g_Gi + z*sa,
                                            g_Er, g_Ei,
                                            g_T2r + z*sc, g_T2i + z*sc);
}

// ---- stage 3: half-plane pointwise multiply by Hermitian part of W + cin sum ----
__global__ void k_pointwise(const float* __restrict__ w) {
    const int p = blockIdx.x * blockDim.x + threadIdx.x;  // ky*511+kx, ky=0..255
    if (p >= HALF) return;
    const int o = blockIdx.y;
    const int ky = p / N5, kx = p - ky * N5;
    const int ky2 = (N5 - ky) % N5;
    const int kx2 = (N5 - kx) % N5;
    const size_t pm = (size_t)ky2 * N5 + kx2;             // mirror index, full plane

    // Front-batch all 8 weight loads (4 coalesced + 4 mirror-gather) for MLP.
    float2 w1v[NCIN], w2v[NCIN];
    #pragma unroll
    for (int c = 0; c < NCIN; c++) {
        const float* wb = w + (size_t)(o*NCIN + c) * PLANE * 2;
        w1v[c] = *reinterpret_cast<const float2*>(wb + (size_t)p * 2);
        w2v[c] = *reinterpret_cast<const float2*>(wb + pm * 2);
    }
    float whr[NCIN], whi[NCIN];
    #pragma unroll
    for (int c = 0; c < NCIN; c++) {
        whr[c] = 0.5f * (w1v[c].x + w2v[c].x);
        whi[c] = 0.5f * (w1v[c].y - w2v[c].y);
    }
    #pragma unroll
    for (int b = 0; b < NB; b++) {
        float gr = 0.f, gi = 0.f;
        #pragma unroll
        for (int c = 0; c < NCIN; c++) {
            const float fr = g_Fr[(size_t)(b*NCIN + c)*HALF + p];
            const float fi = g_Fi[(size_t)(b*NCIN + c)*HALF + p];
            gr += fr * whr[c] - fi * whi[c];
            gi += fr * whi[c] + fi * whr[c];
        }
        g_Gr[(size_t)(b*NCOUT + o)*HALF + p] = gr;
        g_Gi[(size_t)(b*NCOUT + o)*HALF + p] = gi;
    }
}

// ---- stage 5: out[z] (256x256 real) = E5r @ T2r - E5i @ T2i + bias ----
__global__ void k_stage5(const float* __restrict__ bias, float* __restrict__ out) {
    const int z = blockIdx.z;                   // b*NCOUT + o
    const float* __restrict__ Br = g_T2r + (size_t)z * HH * HH;
    const float* __restrict__ Bi = g_T2i + (size_t)z * HH * HH;
    float* __restrict__ O = out + (size_t)z * HH * HH;

    __shared__ float Aer[16][68], Aei[16][68], Bsr[16][68], Bsi[16][68];
    const int tx = threadIdx.x, ty = threadIdx.y;
    const int tid = ty * 16 + tx;
    const int m0 = blockIdx.y * 64, n0 = blockIdx.x * 64;
    const int ra = tid >> 2, ka = (tid & 3) * 4;
    const int kb = tid >> 4, nb = (tid & 15) * 4;

    float acc[4][4] = {};

    for (int k0 = 0; k0 < HH; k0 += 16) {
        {   const int gm = m0 + ra;
            #pragma unroll
            for (int j = 0; j < 4; j++) {
                const int gk = k0 + ka + j;
                Aer[ka + j][ra] = g_E5r[gm*HH + gk];
                Aei[ka + j][ra] = g_E5i[gm*HH + gk];
            }
        }
        {   const int gk = k0 + kb;
            #pragma unroll
            for (int j = 0; j < 4; j++) {
                Bsr[kb][nb + j] = Br[gk*HH + n0 + nb + j];
                Bsi[kb][nb + j] = Bi[gk*HH + n0 + nb + j];
            }
        }
        __syncthreads();
        #pragma unroll
        for (int k = 0; k < 16; k++) {
            float4 erv = *reinterpret_cast<const float4*>(&Aer[k][ty*4]);
            float4 eiv = *reinterpret_cast<const float4*>(&Aei[k][ty*4]);
            float4 brv = *reinterpret_cast<const float4*>(&Bsr[k][tx*4]);
            float4 biv = *reinterpret_cast<const float4*>(&Bsi[k][tx*4]);
            const float er[4] = {erv.x, erv.y, erv.z, erv.w};
            const float ei[4] = {eiv.x, eiv.y, eiv.z, eiv.w};
            const float br[4] = {brv.x, brv.y, brv.z, brv.w};
            const float bi[4] = {biv.x, biv.y, biv.z, biv.w};
            #pragma unroll
            for (int i = 0; i < 4; i++)
                #pragma unroll
                for (int j = 0; j < 4; j++)
                    acc[i][j] += er[i] * br[j] - ei[i] * bi[j];
        }
        __syncthreads();
    }
    const float bv = bias[z & 7];               // z % NCOUT
    #pragma unroll
    for (int i = 0; i < 4; i++) {
        const int gm = m0 + ty*4 + i;
        #pragma unroll
        for (int j = 0; j < 4; j++) {
            const int gn = n0 + tx*4 + j;
            O[gm*HH + gn] = acc[i][j] + bv;
        }
    }
}

extern "C" void kernel_launch(void* const* d_in, const int* in_sizes, int n_in,
                              void* d_out, int out_size) {
    (void)in_sizes; (void)n_in; (void)out_size;
    const float* im   = (const float*)d_in[0];  // [4,4,256,256]
    const float* w    = (const float*)d_in[1];  // [8,4,511,511,2]
    const float* bias = (const float*)d_in[2];  // [8,1,1]
    float* out = (float*)d_out;                 // [4,8,256,256]

    const dim3 blk(16, 16);
    k_twiddle<<<(N5*HH + 255) / 256, 256>>>();
    k_stage1 <<<dim3(4, 4, BC), blk>>>(im);                        // 256x256, K=256
    k_stage2 <<<dim3(8, 4, BC), blk>>>();                          // 256x511, K=256
    k_pointwise<<<dim3((HALF + 255) / 256, NCOUT), 256>>>(w);      // half-plane
    k_stage4 <<<dim3(4, 4, BO), blk>>>();                          // 256x256, K=511
    k_stage5 <<<dim3(4, 4, BO), blk>>>(bias, out);                 // 256x256, K=256
}

// round 4
// speedup vs baseline: 2.0259x; 1.1192x over previous
#include <cuda_runtime.h>

// FourierConv2D via DFT-as-GEMM (fp32) + Hermitian half-plane symmetry.
//   Real input  => F[-k] = conj(F[k])  => only ky=0..255 of the 511-row plane needed.
//   Re(ifft(F*W)) = ifft(F*W_h), W_h = Hermitian part of W  => G stays Hermitian.
//   Final row-inverse folds ky and (511-ky) into one real GEMM with 2x weights.
// kx dimension padded 511->512 (pad entries zero) so all GEMMs are tile-exact
// and float4-aligned. Big-tile GEMM: 64x64 block, 128 thr, 8x4 cplx per thread.

namespace {
constexpr int N5    = 511;
constexpr int HH    = 256;
constexpr int NP    = 512;           // padded kx extent
constexpr int NB    = 4;
constexpr int NCIN  = 4;
constexpr int NCOUT = 8;
constexpr int PLANE = N5 * N5;       // W layout (unpadded full plane)
constexpr int HALFP = HH * NP;       // padded half-plane elements
constexpr int SQ    = HH * HH;       // 65536
constexpr int BC    = NB * NCIN;     // 16
constexpr int BO    = NB * NCOUT;    // 32
}

// ---- scratch (device globals; no allocation allowed) ----
__device__ float g_Ar[NP*HH],  g_Ai[NP*HH];    // A[kx][n] = exp(-2pi i kx n/511); row 511 = 0
__device__ float g_Er[HH*NP],  g_Ei[HH*NP];    // Ec[x][kx]= exp(+2pi i kx (x+127)/511)/511; col 511 = 0
__device__ float g_E5r[HH*HH], g_E5i[HH*HH];   // E5[y][ky]= w(ky) exp(+2pi i ky (y+127)/511), w=1/511 (ky=0) else 2/511
__device__ float g_T1r[BC*SQ],    g_T1i[BC*SQ];
__device__ float g_Fr[BC*HALFP],  g_Fi[BC*HALFP];
__device__ float g_Gr[BO*HALFP],  g_Gi[BO*HALFP];
__device__ float g_T2r[BO*SQ],    g_T2i[BO*SQ];

// ---- twiddle init (recomputed every launch; cheap) ----
__global__ void k_twiddle() {
    const int idx = blockIdx.x * blockDim.x + threadIdx.x;   // 0..131071
    const float TWO_PI = 6.283185307179586f;
    {   // A: [kx 0..511][n 0..255]
        const int k = idx >> 8, n = idx & 255;
        if (k == N5) { g_Ar[idx] = 0.f; g_Ai[idx] = 0.f; }
        else {
            int m = (k * n) % N5;
            float s, c; sincosf(TWO_PI * (float)m / (float)N5, &s, &c);
            g_Ar[idx] = c;  g_Ai[idx] = -s;
        }
    }
    {   // Ec: [x 0..255][kx 0..511]
        const int x = idx >> 9, k = idx & 511;
        if (k == N5) { g_Er[idx] = 0.f; g_Ei[idx] = 0.f; }
        else {
            int m = (k * (x + 127)) % N5;
            float s, c; sincosf(TWO_PI * (float)m / (float)N5, &s, &c);
            const float inv = 1.0f / (float)N5;
            g_Er[idx] = c * inv;  g_Ei[idx] = s * inv;
        }
    }
    if (idx < HH * HH) {
        const int y = idx / HH, ky = idx - y * HH;
        int m = (ky * (y + 127)) % N5;
        float s, c; sincosf(TWO_PI * (float)m / (float)N5, &s, &c);
        const float w = (ky == 0) ? (1.0f / (float)N5) : (2.0f / (float)N5);
        g_E5r[idx] = c * w;  g_E5i[idx] = s * w;
    }
}

// ---- stage 1: T1[z] (256x256 cplx) = A[0:256] (cplx) @ X[z] (256x256 real) ----
__global__ void k_stage1(const float* __restrict__ im) {
    const int z = blockIdx.z;
    const float* __restrict__ X = im + (size_t)z * SQ;
    float* __restrict__ Cr = g_T1r + (size_t)z * SQ;
    float* __restrict__ Ci = g_T1i + (size_t)z * SQ;

    __shared__ float Asr[16][68], Asi[16][68], Bs[16][68];
    const int tx = threadIdx.x, ty = threadIdx.y;
    const int tid = ty * 16 + tx;
    const int m0 = blockIdx.y * 64, n0 = blockIdx.x * 64;
    const int ra = tid >> 2, ka = (tid & 3) * 4;
    const int kb = tid >> 4, nb = (tid & 15) * 4;

    float cr[4][4] = {}, ci[4][4] = {};

    for (int k0 = 0; k0 < HH; k0 += 16) {
        const int gm = m0 + ra;
        #pragma unroll
        for (int j = 0; j < 4; j++) {
            const int gk = k0 + ka + j;
            Asr[ka + j][ra] = g_Ar[gm*HH + gk];
            Asi[ka + j][ra] = g_Ai[gm*HH + gk];
        }
        #pragma unroll
        for (int j = 0; j < 4; j++)
            Bs[kb][nb + j] = X[(k0 + kb)*HH + n0 + nb + j];
        __syncthreads();

        #pragma unroll
        for (int k = 0; k < 16; k++) {
            float4 arv = *reinterpret_cast<const float4*>(&Asr[k][ty*4]);
            float4 aiv = *reinterpret_cast<const float4*>(&Asi[k][ty*4]);
            float4 bv  = *reinterpret_cast<const float4*>(&Bs[k][tx*4]);
            const float ar[4] = {arv.x, arv.y, arv.z, arv.w};
            const float ai[4] = {aiv.x, aiv.y, aiv.z, aiv.w};
            const float b [4] = {bv.x,  bv.y,  bv.z,  bv.w};
            #pragma unroll
            for (int i = 0; i < 4; i++)
                #pragma unroll
                for (int j = 0; j < 4; j++) {
                    cr[i][j] += ar[i] * b[j];
                    ci[i][j] += ai[i] * b[j];
                }
        }
        __syncthreads();
    }
    #pragma unroll
    for (int i = 0; i < 4; i++) {
        const int gm = m0 + ty*4 + i;
        #pragma unroll
        for (int j = 0; j < 4; j++) {
            const int gn = n0 + tx*4 + j;
            Cr[gm*HH + gn] = cr[i][j];
            Ci[gm*HH + gn] = ci[i][j];
        }
    }
}

// ---- big-tile complex GEMM, B transposed: C(MxN) = A(MxK) @ B(NxK)^T ----
// 64x64 block tile, 128 threads, 8x4 cplx per thread. All dims tile-exact.
template<int M, int N, int K>
__device__ __forceinline__ void cgemm_bt(
    const float* __restrict__ Ar, const float* __restrict__ Ai,
    const float* __restrict__ Br, const float* __restrict__ Bi,
    float* __restrict__ Cr, float* __restrict__ Ci)
{
    __shared__ float Asr[16][68], Asi[16][68], Bsr[16][68], Bsi[16][68];
    const int tid = threadIdx.x;                 // 0..127
    const int tx = tid & 15, ty = tid >> 4;      // tx: 16 col-groups, ty: 8 row-groups
    const int m0 = blockIdx.y * 64, n0 = blockIdx.x * 64;
    const int rw = tid >> 1, k8 = (tid & 1) * 8; // loader: row 0..63, k-offset 0/8

    const float* pAr = Ar + (size_t)(m0 + rw)*K + k8;
    const float* pAi = Ai + (size_t)(m0 + rw)*K + k8;
    const float* pBr = Br + (size_t)(n0 + rw)*K + k8;
    const float* pBi = Bi + (size_t)(n0 + rw)*K + k8;

    float cr[8][4] = {}, ci[8][4] = {};

    for (int k0 = 0; k0 < K; k0 += 16) {
        float4 a0 = *reinterpret_cast<const float4*>(pAr);
        float4 a1 = *reinterpret_cast<const float4*>(pAr + 4);
        float4 a2 = *reinterpret_cast<const float4*>(pAi);
        float4 a3 = *reinterpret_cast<const float4*>(pAi + 4);
        float4 b0 = *reinterpret_cast<const float4*>(pBr);
        float4 b1 = *reinterpret_cast<const float4*>(pBr + 4);
        float4 b2 = *reinterpret_cast<const float4*>(pBi);
        float4 b3 = *reinterpret_cast<const float4*>(pBi + 4);
        pAr += 16; pAi += 16; pBr += 16; pBi += 16;

        const float ar8[8] = {a0.x,a0.y,a0.z,a0.w,a1.x,a1.y,a1.z,a1.w};
        const float ai8[8] = {a2.x,a2.y,a2.z,a2.w,a3.x,a3.y,a3.z,a3.w};
        const float br8[8] = {b0.x,b0.y,b0.z,b0.w,b1.x,b1.y,b1.z,b1.w};
        const float bi8[8] = {b2.x,b2.y,b2.z,b2.w,b3.x,b3.y,b3.z,b3.w};
        #pragma unroll
        for (int j = 0; j < 8; j++) {
            Asr[k8 + j][rw] = ar8[j];
            Asi[k8 + j][rw] = ai8[j];
            Bsr[k8 + j][rw] = br8[j];
            Bsi[k8 + j][rw] = bi8[j];
        }
        __syncthreads();

        #pragma unroll 4
        for (int k = 0; k < 16; k++) {
            float4 xr0 = *reinterpret_cast<const float4*>(&Asr[k][ty*8]);
            float4 xr1 = *reinterpret_cast<const float4*>(&Asr[k][ty*8+4]);
            float4 xi0 = *reinterpret_cast<const float4*>(&Asi[k][ty*8]);
            float4 xi1 = *reinterpret_cast<const float4*>(&Asi[k][ty*8+4]);
            float4 yr  = *reinterpret_cast<const float4*>(&Bsr[k][tx*4]);
            float4 yi  = *reinterpret_cast<const float4*>(&Bsi[k][tx*4]);
            const float ar[8] = {xr0.x,xr0.y,xr0.z,xr0.w,xr1.x,xr1.y,xr1.z,xr1.w};
            const float ai[8] = {xi0.x,xi0.y,xi0.z,xi0.w,xi1.x,xi1.y,xi1.z,xi1.w};
            const float br[4] = {yr.x,yr.y,yr.z,yr.w};
            const float bi[4] = {yi.x,yi.y,yi.z,yi.w};
            #pragma unroll
            for (int i = 0; i < 8; i++)
                #pragma unroll
                for (int j = 0; j < 4; j++) {
                    cr[i][j] += ar[i] * br[j] - ai[i] * bi[j];
                    ci[i][j] += ar[i] * bi[j] + ai[i] * br[j];
                }
        }
        __syncthreads();
    }
    #pragma unroll
    for (int i = 0; i < 8; i++) {
        const int gm = m0 + ty*8 + i;
        float4 vr = {cr[i][0], cr[i][1], cr[i][2], cr[i][3]};
        float4 vi = {ci[i][0], ci[i][1], ci[i][2], ci[i][3]};
        *reinterpret_cast<float4*>(&Cr[(size_t)gm*N + n0 + tx*4]) = vr;
        *reinterpret_cast<float4*>(&Ci[(size_t)gm*N + n0 + tx*4]) = vi;
    }
}

// stage 2: F[z] (256x512) = T1[z] (256x256) @ A(512x256)^T   (F col 511 = 0 via A row 511 = 0)
__global__ void __launch_bounds__(128, 4) k_stage2() {
    const int z = blockIdx.z;
    cgemm_bt<HH, NP, HH>(g_T1r + (size_t)z*SQ, g_T1i + (size_t)z*SQ,
                         g_Ar, g_Ai,
                         g_Fr + (size_t)z*HALFP, g_Fi + (size_t)z*HALFP);
}

// stage 4: T2[z] (256x256) = G[z] (256x512) @ Ec(256x512)^T  (Ec col 511 = 0)
__global__ void __launch_bounds__(128, 4) k_stage4() {
    const int z = blockIdx.z;
    cgemm_bt<HH, HH, NP>(g_Gr + (size_t)z*HALFP, g_Gi + (size_t)z*HALFP,
                         g_Er, g_Ei,
                         g_T2r + (size_t)z*SQ, g_T2i + (size_t)z*SQ);
}

// ---- stage 3: half-plane pointwise multiply by Hermitian part of W + cin sum ----
__global__ void k_pointwise(const float* __restrict__ w) {
    const int p = blockIdx.x * blockDim.x + threadIdx.x;  // ky*512+kx
    const int o = blockIdx.y;
    const int ky = p >> 9, kx = p & 511;
    if (kx == N5) {                                        // pad column: zero G
        #pragma unroll
        for (int b = 0; b < NB; b++) {
            g_Gr[(size_t)(b*NCOUT + o)*HALFP + p] = 0.f;
            g_Gi[(size_t)(b*NCOUT + o)*HALFP + p] = 0.f;
        }
        return;
    }
    const int ky2 = (N5 - ky) % N5;
    const int kx2 = (N5 - kx) % N5;
    const size_t pw = (size_t)ky * N5 + kx;               // W index (unpadded)
    const size_t pm = (size_t)ky2 * N5 + kx2;             // mirror index

    float2 w1v[NCIN], w2v[NCIN];
    #pragma unroll
    for (int c = 0; c < NCIN; c++) {
        const float* wb = w + (size_t)(o*NCIN + c) * PLANE * 2;
        w1v[c] = *reinterpret_cast<const float2*>(wb + pw * 2);
        w2v[c] = *reinterpret_cast<const float2*>(wb + pm * 2);
    }
    float whr[NCIN], whi[NCIN];
    #pragma unroll
    for (int c = 0; c < NCIN; c++) {
        whr[c] = 0.5f * (w1v[c].x + w2v[c].x);
        whi[c] = 0.5f * (w1v[c].y - w2v[c].y);
    }
    #pragma unroll
    for (int b = 0; b < NB; b++) {
        float gr = 0.f, gi = 0.f;
        #pragma unroll
        for (int c = 0; c < NCIN; c++) {
            const float fr = g_Fr[(size_t)(b*NCIN + c)*HALFP + p];
            const float fi = g_Fi[(size_t)(b*NCIN + c)*HALFP + p];
            gr += fr * whr[c] - fi * whi[c];
            gi += fr * whi[c] + fi * whr[c];
        }
        g_Gr[(size_t)(b*NCOUT + o)*HALFP + p] = gr;
        g_Gi[(size_t)(b*NCOUT + o)*HALFP + p] = gi;
    }
}

// ---- stage 5: out[z] = E5r @ T2r - E5i @ T2i + bias (real; B in [k][n] layout) ----
__global__ void __launch_bounds__(128, 4) k_stage5(const float* __restrict__ bias,
                                                   float* __restrict__ out) {
    const int z = blockIdx.z;                   // b*NCOUT + o
    const float* __restrict__ Br = g_T2r + (size_t)z * SQ;
    const float* __restrict__ Bi = g_T2i + (size_t)z * SQ;
    float* __restrict__ O = out + (size_t)z * SQ;

    __shared__ float Asr[16][68], Asi[16][68], Bsr[16][68], Bsi[16][68];
    const int tid = threadIdx.x;                 // 0..127
    const int tx = tid & 15, ty = tid >> 4;
    const int m0 = blockIdx.y * 64, n0 = blockIdx.x * 64;
    const int rw = tid >> 1, k8 = (tid & 1) * 8;          // A loader
    const int kb0 = (tid >> 4) * 2, nb0 = (tid & 15) * 4; // B loader: 2 k-rows, 4 cols

    const float* pAr = g_E5r + (size_t)(m0 + rw)*HH + k8;
    const float* pAi = g_E5i + (size_t)(m0 + rw)*HH + k8;

    float acc[8][4] = {};

    for (int k0 = 0; k0 < HH; k0 += 16) {
        float4 a0 = *reinterpret_cast<const float4*>(pAr);
        float4 a1 = *reinterpret_cast<const float4*>(pAr + 4);
        float4 a2 = *reinterpret_cast<const float4*>(pAi);
        float4 a3 = *reinterpret_cast<const float4*>(pAi + 4);
        pAr += 16; pAi += 16;
        float4 br0 = *reinterpret_cast<const float4*>(&Br[(size_t)(k0 + kb0)*HH + n0 + nb0]);
        float4 br1 = *reinterpret_cast<const float4*>(&Br[(size_t)(k0 + kb0 + 1)*HH + n0 + nb0]);
        float4 bi0 = *reinterpret_cast<const float4*>(&Bi[(size_t)(k0 + kb0)*HH + n0 + nb0]);
        float4 bi1 = *reinterpret_cast<const float4*>(&Bi[(size_t)(k0 + kb0 + 1)*HH + n0 + nb0]);

        const float ar8[8] = {a0.x,a0.y,a0.z,a0.w,a1.x,a1.y,a1.z,a1.w};
        const float ai8[8] = {a2.x,a2.y,a2.z,a2.w,a3.x,a3.y,a3.z,a3.w};
        #pragma unroll
        for (int j = 0; j < 8; j++) {
            Asr[k8 + j][rw] = ar8[j];
            Asi[k8 + j][rw] = ai8[j];
        }
        *reinterpret_cast<float4*>(&Bsr[kb0][nb0])     = br0;
        *reinterpret_cast<float4*>(&Bsr[kb0 + 1][nb0]) = br1;
        *reinterpret_cast<float4*>(&Bsi[kb0][nb0])     = bi0;
        *reinterpret_cast<float4*>(&Bsi[kb0 + 1][nb0]) = bi1;
        __syncthreads();

        #pragma unroll 4
        for (int k = 0; k < 16; k++) {
            float4 xr0 = *reinterpret_cast<const float4*>(&Asr[k][ty*8]);
            float4 xr1 = *reinterpret_cast<const float4*>(&Asr[k][ty*8+4]);
            float4 xi0 = *reinterpret_cast<const float4*>(&Asi[k][ty*8]);
            float4 xi1 = *reinterpret_cast<const float4*>(&Asi[k][ty*8+4]);
            float4 yr  = *reinterpret_cast<const float4*>(&Bsr[k][tx*4]);
            float4 yi  = *reinterpret_cast<const float4*>(&Bsi[k][tx*4]);
            const float er[8] = {xr0.x,xr0.y,xr0.z,xr0.w,xr1.x,xr1.y,xr1.z,xr1.w};
            const float ei[8] = {xi0.x,xi0.y,xi0.z,xi0.w,xi1.x,xi1.y,xi1.z,xi1.w};
            const float br[4] = {yr.x,yr.y,yr.z,yr.w};
            const float bi[4] = {yi.x,yi.y,yi.z,yi.w};
            #pragma unroll
            for (int i = 0; i < 8; i++)
                #pragma unroll
                for (int j = 0; j < 4; j++)
                    acc[i][j] += er[i] * br[j] - ei[i] * bi[j];
        }
        __syncthreads();
    }
    const float bv = bias[z & 7];
    #pragma unroll
    for (int i = 0; i < 8; i++) {
        const int gm = m0 + ty*8 + i;
        float4 v = {acc[i][0] + bv, acc[i][1] + bv, acc[i][2] + bv, acc[i][3] + bv};
        *reinterpret_cast<float4*>(&O[(size_t)gm*HH + n0 + tx*4]) = v;
    }
}

extern "C" void kernel_launch(void* const* d_in, const int* in_sizes, int n_in,
                              void* d_out, int out_size) {
    (void)in_sizes; (void)n_in; (void)out_size;
    const float* im   = (const float*)d_in[0];  // [4,4,256,256]
    const float* w    = (const float*)d_in[1];  // [8,4,511,511,2]
    const float* bias = (const float*)d_in[2];  // [8,1,1]
    float* out = (float*)d_out;                 // [4,8,256,256]

    k_twiddle<<<512, 256>>>();
    k_stage1 <<<dim3(4, 4, BC), dim3(16, 16)>>>(im);        // 256x256, K=256
    k_stage2 <<<dim3(8, 4, BC), 128>>>();                   // 256x512, K=256
    k_pointwise<<<dim3(HALFP / 256, NCOUT), 256>>>(w);      // padded half-plane
    k_stage4 <<<dim3(4, 4, BO), 128>>>();                   // 256x256, K=512
    k_stage5 <<<dim3(4, 4, BO), 128>>>(bias, out);          // 256x256, K=256
}